// round 7
// baseline (speedup 1.0000x reference)
#include <cuda_runtime.h>
#include <cuda_fp16.h>

#define HD   160
#define PLN  25600          // W*D
#define VOL  4096000        // H*W*D
#define NVOX 8192000ULL     // 2*160^3
#define WCH  16             // P1 w-rows per block
#define SEG  40             // P2/P3 slide segment
#define NBBC 1280           // P3 grid blocks: 4*160*2

// Normalized 1D Gaussian, KS=11, sigma=1.5
__device__ constexpr float GW[11] = {
    0.00102838f, 0.00759876f, 0.03600077f, 0.10936070f, 0.21300553f,
    0.26601172f,
    0.21300553f, 0.10936070f, 0.03600077f, 0.00759876f, 0.00102838f
};

constexpr float C1f  = 1.0e-4f;
constexpr float C2f  = 9.0e-4f;
constexpr float EPSf = 1.0e-12f;

// fp16 scratch: gA = D-blurred fields, gC = D+W-blurred fields.
__device__ __half gA[5ULL * NVOX];
__device__ __half gC[5ULL * NVOX];
__device__ double g_acc;
__device__ unsigned int g_ticket;

__device__ __forceinline__ int refl(int i) {
    return (i < 0) ? -i : ((i > HD - 1) ? (2 * (HD - 1) - i) : i);
}

// ---------------------------------------------------------------------------
// P1: D-blur + product fields. Block (w-chunk 16, h, b), 160 threads.
// Raw rows in padded smem; each thread handles a d-pair via a 14-float
// register window (7 LDS.64). Products shared within the pair.
// ---------------------------------------------------------------------------
__global__ void __launch_bounds__(HD) passD(const float* __restrict__ src,
                                            const float* __restrict__ ref) {
    __shared__ float S[WCH][172];
    __shared__ float R[WCH][172];

    const int t  = threadIdx.x;
    const int b  = blockIdx.z;
    const int h  = blockIdx.y;
    const int w0 = blockIdx.x * WCH;

    const size_t bh = ((size_t)(b * HD + h)) * PLN;

    for (int row = 0; row < WCH; ++row) {
        const float* ps = src + bh + (size_t)(w0 + row) * HD;
        const float* pr = ref + bh + (size_t)(w0 + row) * HD;
        S[row][6 + t] = __ldg(ps + t);
        R[row][6 + t] = __ldg(pr + t);
        if (t < 6)    { S[row][t]      = __ldg(ps + 6 - t);   R[row][t]      = __ldg(pr + 6 - t); }
        if (t >= 154) { S[row][t + 12] = __ldg(ps + 312 - t); R[row][t + 12] = __ldg(pr + 312 - t); }
    }
    __syncthreads();

    const int rp = t / 80;          // which row of each pair
    const int tp = t % 80;          // d-pair index

    for (int it = 0; it < WCH / 2; ++it) {
        const int row = it * 2 + rp;
        float ws[14], wr[14];
        const float2* s2 = reinterpret_cast<const float2*>(&S[row][0]) + tp;
        const float2* r2 = reinterpret_cast<const float2*>(&R[row][0]) + tp;
        #pragma unroll
        for (int p = 0; p < 7; ++p) {
            const float2 a = s2[p]; ws[2 * p] = a.x; ws[2 * p + 1] = a.y;
            const float2 c = r2[p]; wr[2 * p] = c.x; wr[2 * p + 1] = c.y;
        }

        float a0x = 0.f, a1x = 0.f, a2x = 0.f, a3x = 0.f, a4x = 0.f;
        float a0y = 0.f, a1y = 0.f, a2y = 0.f, a3y = 0.f, a4y = 0.f;

        #pragma unroll
        for (int k = 0; k < 11; ++k) {
            const float s = ws[1 + k], v = wr[1 + k];
            const float ss = s * s, vv = v * v, sv = s * v;
            a0x = fmaf(GW[k], s,  a0x);
            a1x = fmaf(GW[k], v,  a1x);
            a2x = fmaf(GW[k], ss, a2x);
            a3x = fmaf(GW[k], vv, a3x);
            a4x = fmaf(GW[k], sv, a4x);
            if (k >= 1) {
                a0y = fmaf(GW[k - 1], s,  a0y);
                a1y = fmaf(GW[k - 1], v,  a1y);
                a2y = fmaf(GW[k - 1], ss, a2y);
                a3y = fmaf(GW[k - 1], vv, a3y);
                a4y = fmaf(GW[k - 1], sv, a4y);
            }
        }
        {
            const float s = ws[12], v = wr[12];
            const float ss = s * s, vv = v * v, sv = s * v;
            a0y = fmaf(GW[10], s,  a0y);
            a1y = fmaf(GW[10], v,  a1y);
            a2y = fmaf(GW[10], ss, a2y);
            a3y = fmaf(GW[10], vv, a3y);
            a4y = fmaf(GW[10], sv, a4y);
        }

        const size_t hoff = (bh + (size_t)(w0 + row) * HD) / 2 + tp;
        reinterpret_cast<__half2*>(gA + 0ULL * NVOX)[hoff] = __floats2half2_rn(a0x, a0y);
        reinterpret_cast<__half2*>(gA + 1ULL * NVOX)[hoff] = __floats2half2_rn(a1x, a1y);
        reinterpret_cast<__half2*>(gA + 2ULL * NVOX)[hoff] = __floats2half2_rn(a2x, a2y);
        reinterpret_cast<__half2*>(gA + 3ULL * NVOX)[hoff] = __floats2half2_rn(a3x, a3y);
        reinterpret_cast<__half2*>(gA + 4ULL * NVOX)[hoff] = __floats2half2_rn(a4x, a4y);
    }
}

// ---------------------------------------------------------------------------
// P2: W-blur. Thread owns (b,h,d), slides w over SEG with an 11-slot fp32
// register ring, PREFETCH DISTANCE 1: plane j+6 is loaded into temporaries,
// retired into slot u after the compute that reads slot u's old plane (j-5).
// ---------------------------------------------------------------------------
__global__ void __launch_bounds__(HD) passW() {
    const int d  = threadIdx.x;
    const int b  = blockIdx.z;
    const int h  = blockIdx.y;
    const int w0 = blockIdx.x * SEG;

    const size_t bh = ((size_t)(b * HD + h)) * PLN;

    float win[5][11];

    #pragma unroll
    for (int m = 0; m < 11; ++m) {              // planes w0-5 .. w0+5 -> slot m
        const size_t off = bh + (size_t)refl(w0 - 5 + m) * HD + d;
        #pragma unroll
        for (int f = 0; f < 5; ++f)
            win[f][m] = __half2float(__ldg(gA + (size_t)f * NVOX + off));
    }

    #pragma unroll 1
    for (int c = 0; c < SEG / 11 + 1; ++c) {
        const int jbase = c * 11;
        #pragma unroll
        for (int u = 0; u < 11; ++u) {
            const int j = jbase + u;
            if (j >= SEG) break;
            // Prefetch plane w0+j+6 (consumed next iteration).
            float t0, t1, t2, t3, t4;
            {
                const size_t off = bh + (size_t)refl(w0 + j + 6) * HD + d;
                t0 = __half2float(__ldg(gA + 0ULL * NVOX + off));
                t1 = __half2float(__ldg(gA + 1ULL * NVOX + off));
                t2 = __half2float(__ldg(gA + 2ULL * NVOX + off));
                t3 = __half2float(__ldg(gA + 3ULL * NVOX + off));
                t4 = __half2float(__ldg(gA + 4ULL * NVOX + off));
            }
            float o0 = 0.f, o1 = 0.f, o2 = 0.f, o3 = 0.f, o4 = 0.f;
            #pragma unroll
            for (int k = 0; k < 11; ++k) {
                const int sl = (u + k) % 11;
                o0 = fmaf(GW[k], win[0][sl], o0);
                o1 = fmaf(GW[k], win[1][sl], o1);
                o2 = fmaf(GW[k], win[2][sl], o2);
                o3 = fmaf(GW[k], win[3][sl], o3);
                o4 = fmaf(GW[k], win[4][sl], o4);
            }
            const size_t oo = bh + (size_t)(w0 + j) * HD + d;
            gC[0ULL * NVOX + oo] = __float2half_rn(o0);
            gC[1ULL * NVOX + oo] = __float2half_rn(o1);
            gC[2ULL * NVOX + oo] = __float2half_rn(o2);
            gC[3ULL * NVOX + oo] = __float2half_rn(o3);
            gC[4ULL * NVOX + oo] = __float2half_rn(o4);
            // Retire prefetch into slot u (old plane j-5, already consumed at k=0).
            win[0][u] = t0; win[1][u] = t1; win[2][u] = t2;
            win[3][u] = t3; win[4][u] = t4;
        }
    }
}

// ---------------------------------------------------------------------------
// P3: H-blur + SSIM + reduce. Same prefetched ring sliding h (stride PLN).
// ---------------------------------------------------------------------------
__global__ void __launch_bounds__(HD) passH(float* __restrict__ out) {
    const int d  = threadIdx.x;
    const int b  = blockIdx.z;
    const int w  = blockIdx.y;
    const int h0 = blockIdx.x * SEG;

    const size_t bw = (size_t)b * VOL + (size_t)w * HD + d;

    float win[5][11];

    #pragma unroll
    for (int m = 0; m < 11; ++m) {
        const size_t off = bw + (size_t)refl(h0 - 5 + m) * PLN;
        #pragma unroll
        for (int f = 0; f < 5; ++f)
            win[f][m] = __half2float(__ldg(gC + (size_t)f * NVOX + off));
    }

    float acc = 0.f;

    #pragma unroll 1
    for (int c = 0; c < SEG / 11 + 1; ++c) {
        const int jbase = c * 11;
        #pragma unroll
        for (int u = 0; u < 11; ++u) {
            const int j = jbase + u;
            if (j >= SEG) break;
            float t0, t1, t2, t3, t4;
            {
                const size_t off = bw + (size_t)refl(h0 + j + 6) * PLN;
                t0 = __half2float(__ldg(gC + 0ULL * NVOX + off));
                t1 = __half2float(__ldg(gC + 1ULL * NVOX + off));
                t2 = __half2float(__ldg(gC + 2ULL * NVOX + off));
                t3 = __half2float(__ldg(gC + 3ULL * NVOX + off));
                t4 = __half2float(__ldg(gC + 4ULL * NVOX + off));
            }
            float mu1 = 0.f, mu2 = 0.f, m11 = 0.f, m22 = 0.f, m12 = 0.f;
            #pragma unroll
            for (int k = 0; k < 11; ++k) {
                const int sl = (u + k) % 11;
                mu1 = fmaf(GW[k], win[0][sl], mu1);
                mu2 = fmaf(GW[k], win[1][sl], mu2);
                m11 = fmaf(GW[k], win[2][sl], m11);
                m22 = fmaf(GW[k], win[3][sl], m22);
                m12 = fmaf(GW[k], win[4][sl], m12);
            }
            const float a  = mu1 * mu1;
            const float bb = mu2 * mu2;
            const float cc = mu1 * mu2;
            const float s1 = m11 - a, s2 = m22 - bb, s12 = m12 - cc;
            const float num = (2.f * cc + C1f) * (2.f * s12 + C2f);
            const float den = (a + bb + C1f) * (s1 + s2 + C2f);
            acc += __fdividef(num, den + EPSf);
            win[0][u] = t0; win[1][u] = t1; win[2][u] = t2;
            win[3][u] = t3; win[4][u] = t4;
        }
    }

    // Reduce: 5 warps -> smem -> atomicAdd(double), ticket finalize.
    float v = acc;
    #pragma unroll
    for (int o = 16; o > 0; o >>= 1) v += __shfl_down_sync(0xffffffffu, v, o);
    __shared__ float ws[5];
    if ((threadIdx.x & 31) == 0) ws[threadIdx.x >> 5] = v;
    __syncthreads();
    if (threadIdx.x == 0) {
        const float s = ws[0] + ws[1] + ws[2] + ws[3] + ws[4];
        atomicAdd(&g_acc, (double)s);
        __threadfence();
        const unsigned done = atomicAdd(&g_ticket, 1u);
        if (done == NBBC - 1) {
            const double vv = atomicAdd(&g_acc, 0.0);
            out[0] = (float)(1.0 - vv / (double)NVOX);
            g_acc = 0.0;
            g_ticket = 0u;
            __threadfence();
        }
    }
}

extern "C" void kernel_launch(void* const* d_in, const int* in_sizes, int n_in,
                              void* d_out, int out_size) {
    const float* src = (const float*)d_in[0];
    const float* ref = (const float*)d_in[1];
    float* out = (float*)d_out;

    passD<<<dim3(HD / WCH, HD, 2), HD>>>(src, ref);
    passW<<<dim3(HD / SEG, HD, 2), HD>>>();
    passH<<<dim3(HD / SEG, HD, 2), HD>>>(out);
}

// round 8
// speedup vs baseline: 1.0884x; 1.0884x over previous
#include <cuda_runtime.h>
#include <cuda_fp16.h>

#define HD   160
#define PLN  25600          // W*D
#define VOL  4096000        // H*W*D
#define NVOX 8192000ULL     // 2*160^3
#define WCH  16             // P1 w-rows per block
#define SEG  40             // P2/P3 slide segment
#define NSEG 4              // HD/SEG
#define NBBC 1280           // P3 grid blocks: 4*160*2

// Normalized 1D Gaussian, KS=11, sigma=1.5
__device__ constexpr float GW[11] = {
    0.00102838f, 0.00759876f, 0.03600077f, 0.10936070f, 0.21300553f,
    0.26601172f,
    0.21300553f, 0.10936070f, 0.03600077f, 0.00759876f, 0.00102838f
};

constexpr float C1f  = 1.0e-4f;
constexpr float C2f  = 9.0e-4f;
constexpr float EPSf = 1.0e-12f;

// fp16 scratch: gA = D-blurred fields, gC = D+W-blurred fields.
__device__ __half gA[5ULL * NVOX];
__device__ __half gC[5ULL * NVOX];
__device__ double g_acc;
__device__ unsigned int g_ticket;

__device__ __forceinline__ int refl(int i) {
    return (i < 0) ? -i : ((i > HD - 1) ? (2 * (HD - 1) - i) : i);
}

// ---------------------------------------------------------------------------
// P1: D-blur + product fields. Block (w-chunk 16, h, b), 160 threads.
// (unchanged from R6 — measured 51.5 us)
// ---------------------------------------------------------------------------
__global__ void __launch_bounds__(HD) passD(const float* __restrict__ src,
                                            const float* __restrict__ ref) {
    __shared__ float S[WCH][172];
    __shared__ float R[WCH][172];

    const int t  = threadIdx.x;
    const int b  = blockIdx.z;
    const int h  = blockIdx.y;
    const int w0 = blockIdx.x * WCH;

    const size_t bh = ((size_t)(b * HD + h)) * PLN;

    for (int row = 0; row < WCH; ++row) {
        const float* ps = src + bh + (size_t)(w0 + row) * HD;
        const float* pr = ref + bh + (size_t)(w0 + row) * HD;
        S[row][6 + t] = __ldg(ps + t);
        R[row][6 + t] = __ldg(pr + t);
        if (t < 6)    { S[row][t]      = __ldg(ps + 6 - t);   R[row][t]      = __ldg(pr + 6 - t); }
        if (t >= 154) { S[row][t + 12] = __ldg(ps + 312 - t); R[row][t + 12] = __ldg(pr + 312 - t); }
    }
    __syncthreads();

    const int rp = t / 80;
    const int tp = t % 80;

    for (int it = 0; it < WCH / 2; ++it) {
        const int row = it * 2 + rp;
        float ws[14], wr[14];
        const float2* s2 = reinterpret_cast<const float2*>(&S[row][0]) + tp;
        const float2* r2 = reinterpret_cast<const float2*>(&R[row][0]) + tp;
        #pragma unroll
        for (int p = 0; p < 7; ++p) {
            const float2 a = s2[p]; ws[2 * p] = a.x; ws[2 * p + 1] = a.y;
            const float2 c = r2[p]; wr[2 * p] = c.x; wr[2 * p + 1] = c.y;
        }

        float a0x = 0.f, a1x = 0.f, a2x = 0.f, a3x = 0.f, a4x = 0.f;
        float a0y = 0.f, a1y = 0.f, a2y = 0.f, a3y = 0.f, a4y = 0.f;

        #pragma unroll
        for (int k = 0; k < 11; ++k) {
            const float s = ws[1 + k], v = wr[1 + k];
            const float ss = s * s, vv = v * v, sv = s * v;
            a0x = fmaf(GW[k], s,  a0x);
            a1x = fmaf(GW[k], v,  a1x);
            a2x = fmaf(GW[k], ss, a2x);
            a3x = fmaf(GW[k], vv, a3x);
            a4x = fmaf(GW[k], sv, a4x);
            if (k >= 1) {
                a0y = fmaf(GW[k - 1], s,  a0y);
                a1y = fmaf(GW[k - 1], v,  a1y);
                a2y = fmaf(GW[k - 1], ss, a2y);
                a3y = fmaf(GW[k - 1], vv, a3y);
                a4y = fmaf(GW[k - 1], sv, a4y);
            }
        }
        {
            const float s = ws[12], v = wr[12];
            const float ss = s * s, vv = v * v, sv = s * v;
            a0y = fmaf(GW[10], s,  a0y);
            a1y = fmaf(GW[10], v,  a1y);
            a2y = fmaf(GW[10], ss, a2y);
            a3y = fmaf(GW[10], vv, a3y);
            a4y = fmaf(GW[10], sv, a4y);
        }

        const size_t hoff = (bh + (size_t)(w0 + row) * HD) / 2 + tp;
        reinterpret_cast<__half2*>(gA + 0ULL * NVOX)[hoff] = __floats2half2_rn(a0x, a0y);
        reinterpret_cast<__half2*>(gA + 1ULL * NVOX)[hoff] = __floats2half2_rn(a1x, a1y);
        reinterpret_cast<__half2*>(gA + 2ULL * NVOX)[hoff] = __floats2half2_rn(a2x, a2y);
        reinterpret_cast<__half2*>(gA + 3ULL * NVOX)[hoff] = __floats2half2_rn(a3x, a3y);
        reinterpret_cast<__half2*>(gA + 4ULL * NVOX)[hoff] = __floats2half2_rn(a4x, a4y);
    }
}

// ---------------------------------------------------------------------------
// P2: W-blur, FIELD-SPLIT. Block = (field*wseg, h, b), 160 threads.
// Each block blurs ONE field over one w-segment: 11-reg ring + 1-temp
// prefetch (distance 1). Tiny register footprint -> high occupancy.
// ---------------------------------------------------------------------------
__global__ void __launch_bounds__(HD) passW() {
    const int d  = threadIdx.x;
    const int b  = blockIdx.z;
    const int h  = blockIdx.y;
    const int f  = blockIdx.x / NSEG;
    const int w0 = (blockIdx.x % NSEG) * SEG;

    const size_t bh = ((size_t)(b * HD + h)) * PLN;
    const __half* __restrict__ in  = gA + (size_t)f * NVOX;
    __half* __restrict__       outp = gC + (size_t)f * NVOX;

    float win[11];

    #pragma unroll
    for (int m = 0; m < 11; ++m)                 // planes w0-5 .. w0+5
        win[m] = __half2float(__ldg(in + bh + (size_t)refl(w0 - 5 + m) * HD + d));

    #pragma unroll 1
    for (int c = 0; c < SEG / 11 + 1; ++c) {
        const int jbase = c * 11;
        #pragma unroll
        for (int u = 0; u < 11; ++u) {
            const int j = jbase + u;
            if (j >= SEG) break;
            // prefetch plane w0+j+6 (used next iteration)
            const float t = __half2float(
                __ldg(in + bh + (size_t)refl(w0 + j + 6) * HD + d));
            float o = 0.f;
            #pragma unroll
            for (int k = 0; k < 11; ++k)
                o = fmaf(GW[k], win[(u + k) % 11], o);
            outp[bh + (size_t)(w0 + j) * HD + d] = __float2half_rn(o);
            win[u] = t;     // retire (old plane j-5 consumed at k=0)
        }
    }
}

// ---------------------------------------------------------------------------
// P3: H-blur + SSIM + reduce. R6 form (no explicit prefetch), sliding h.
// ---------------------------------------------------------------------------
__global__ void __launch_bounds__(HD) passH(float* __restrict__ out) {
    const int d  = threadIdx.x;
    const int b  = blockIdx.z;
    const int w  = blockIdx.y;
    const int h0 = blockIdx.x * SEG;

    const size_t bw = (size_t)b * VOL + (size_t)w * HD + d;

    float win[5][11];

    #pragma unroll
    for (int m = 0; m < 10; ++m) {
        const size_t off = bw + (size_t)refl(h0 - 5 + m) * PLN;
        #pragma unroll
        for (int f = 0; f < 5; ++f)
            win[f][m] = __half2float(__ldg(gC + (size_t)f * NVOX + off));
    }

    float acc = 0.f;

    #pragma unroll 1
    for (int c = 0; c < SEG / 11 + 1; ++c) {
        const int jbase = c * 11;
        #pragma unroll
        for (int u = 0; u < 11; ++u) {
            const int j = jbase + u;
            if (j >= SEG) break;
            {
                const size_t off = bw + (size_t)refl(h0 + j + 5) * PLN;
                #pragma unroll
                for (int f = 0; f < 5; ++f)
                    win[f][(u + 10) % 11] =
                        __half2float(__ldg(gC + (size_t)f * NVOX + off));
            }
            float mu1 = 0.f, mu2 = 0.f, m11 = 0.f, m22 = 0.f, m12 = 0.f;
            #pragma unroll
            for (int k = 0; k < 11; ++k) {
                const int sl = (u + k) % 11;
                mu1 = fmaf(GW[k], win[0][sl], mu1);
                mu2 = fmaf(GW[k], win[1][sl], mu2);
                m11 = fmaf(GW[k], win[2][sl], m11);
                m22 = fmaf(GW[k], win[3][sl], m22);
                m12 = fmaf(GW[k], win[4][sl], m12);
            }
            const float a  = mu1 * mu1;
            const float bb = mu2 * mu2;
            const float cc = mu1 * mu2;
            const float s1 = m11 - a, s2 = m22 - bb, s12 = m12 - cc;
            const float num = (2.f * cc + C1f) * (2.f * s12 + C2f);
            const float den = (a + bb + C1f) * (s1 + s2 + C2f);
            acc += __fdividef(num, den + EPSf);
        }
    }

    // Reduce: 5 warps -> smem -> atomicAdd(double), ticket finalize.
    float v = acc;
    #pragma unroll
    for (int o = 16; o > 0; o >>= 1) v += __shfl_down_sync(0xffffffffu, v, o);
    __shared__ float ws[5];
    if ((threadIdx.x & 31) == 0) ws[threadIdx.x >> 5] = v;
    __syncthreads();
    if (threadIdx.x == 0) {
        const float s = ws[0] + ws[1] + ws[2] + ws[3] + ws[4];
        atomicAdd(&g_acc, (double)s);
        __threadfence();
        const unsigned done = atomicAdd(&g_ticket, 1u);
        if (done == NBBC - 1) {
            const double vv = atomicAdd(&g_acc, 0.0);
            out[0] = (float)(1.0 - vv / (double)NVOX);
            g_acc = 0.0;
            g_ticket = 0u;
            __threadfence();
        }
    }
}

extern "C" void kernel_launch(void* const* d_in, const int* in_sizes, int n_in,
                              void* d_out, int out_size) {
    const float* src = (const float*)d_in[0];
    const float* ref = (const float*)d_in[1];
    float* out = (float*)d_out;

    passD<<<dim3(HD / WCH, HD, 2), HD>>>(src, ref);
    passW<<<dim3(5 * NSEG, HD, 2), HD>>>();
    passH<<<dim3(NSEG, HD, 2), HD>>>(out);
}

// round 9
// speedup vs baseline: 1.2367x; 1.1363x over previous
#include <cuda_runtime.h>
#include <cuda_fp16.h>

#define HD   160
#define PLN  25600          // W*D
#define VOL  4096000        // H*W*D
#define NVOX 8192000ULL     // 2*160^3
#define WSEG 80             // passDW w-outputs per block
#define NR   90             // rows processed per passDW block (WSEG + 10)
#define PRE  4              // smem prefetch depth (rows)
#define RING 6              // smem row-ring slots (>= PRE+2)
#define SEG  40             // passH slide segment
#define NSEG 4              // HD/SEG
#define NBBC 1280           // passH grid blocks: 4*160*2

// Normalized 1D Gaussian, KS=11, sigma=1.5
__device__ constexpr float GW[11] = {
    0.00102838f, 0.00759876f, 0.03600077f, 0.10936070f, 0.21300553f,
    0.26601172f,
    0.21300553f, 0.10936070f, 0.03600077f, 0.00759876f, 0.00102838f
};

constexpr float C1f  = 1.0e-4f;
constexpr float C2f  = 9.0e-4f;
constexpr float EPSf = 1.0e-12f;

// fp16 scratch: gC = D+W-blurred fields.
__device__ __half gC[5ULL * NVOX];
__device__ double g_acc;
__device__ unsigned int g_ticket;

__device__ __forceinline__ int refl(int i) {
    return (i < 0) ? -i : ((i > HD - 1) ? (2 * (HD - 1) - i) : i);
}

// ---------------------------------------------------------------------------
// passDW: fused D-blur (+5 field products) and W-blur.
// Block = (w-half 80, h, b), 160 threads (t = d).
// smem: RING raw rows of s,r (padded 172, d-reflected).
// Per iteration j (row w0-5+j): one barrier; STS prefetched row j+PRE;
// LDG row j+PRE+1 into registers; D-blur row j from smem into an 11-slot
// register ring (5 fields); if j>=10 emit W-blurred output w0+j-10 as fp16.
// ---------------------------------------------------------------------------
__global__ void __launch_bounds__(HD) passDW(const float* __restrict__ src,
                                             const float* __restrict__ ref) {
    __shared__ float S[RING][172];
    __shared__ float R[RING][172];

    const int t  = threadIdx.x;
    const int b  = blockIdx.z;
    const int h  = blockIdx.y;
    const int w0 = blockIdx.x * WSEG;

    const size_t bh = ((size_t)(b * HD + h)) * PLN;

    const bool loT = (t < 6);
    const bool hiT = (t >= 154);
    const int  hpos = loT ? t : (t + 12);            // halo smem position
    const int  hgl  = loT ? (6 - t) : (312 - t);     // halo global d

    // Prologue: rows 0..PRE-1 straight into smem.
    for (int m = 0; m < PRE; ++m) {
        const size_t base = bh + (size_t)refl(w0 - 5 + m) * HD;
        S[m][6 + t] = __ldg(src + base + t);
        R[m][6 + t] = __ldg(ref + base + t);
        if (loT || hiT) {
            S[m][hpos] = __ldg(src + base + hgl);
            R[m][hpos] = __ldg(ref + base + hgl);
        }
    }
    // Prefetch row PRE into registers.
    float sM, rM, sH = 0.f, rH = 0.f;
    {
        const size_t base = bh + (size_t)refl(w0 - 5 + PRE) * HD;
        sM = __ldg(src + base + t);
        rM = __ldg(ref + base + t);
        if (loT || hiT) { sH = __ldg(src + base + hgl); rH = __ldg(ref + base + hgl); }
    }

    // Register ring of D-blurred fields.
    float q0[11], q1[11], q2[11], q3[11], q4[11];

    int scur = 0;        // j % RING
    int spre = PRE;      // (j+PRE) % RING

    #pragma unroll 1
    for (int c = 0; c < 9; ++c) {
        #pragma unroll
        for (int u = 0; u < 11; ++u) {
            const int j = c * 11 + u;
            if (j >= NR) break;
            __syncthreads();

            // Retire prefetched row j+PRE into smem, then prefetch j+PRE+1.
            if (j + PRE < NR) {
                S[spre][6 + t] = sM;
                R[spre][6 + t] = rM;
                if (loT || hiT) { S[spre][hpos] = sH; R[spre][hpos] = rH; }
                if (j + PRE + 1 < NR) {
                    const size_t base = bh + (size_t)refl(w0 - 5 + j + PRE + 1) * HD;
                    sM = __ldg(src + base + t);
                    rM = __ldg(ref + base + t);
                    if (loT || hiT) { sH = __ldg(src + base + hgl); rH = __ldg(ref + base + hgl); }
                }
            }

            // D-blur row j (slot scur) -> ring slot u (== j % 11).
            float a0 = 0.f, a1 = 0.f, a2 = 0.f, a3 = 0.f, a4 = 0.f;
            #pragma unroll
            for (int k = 0; k < 11; ++k) {
                const float s = S[scur][t + 1 + k];
                const float v = R[scur][t + 1 + k];
                const float ss = s * s, vv = v * v, sv = s * v;
                a0 = fmaf(GW[k], s,  a0);
                a1 = fmaf(GW[k], v,  a1);
                a2 = fmaf(GW[k], ss, a2);
                a3 = fmaf(GW[k], vv, a3);
                a4 = fmaf(GW[k], sv, a4);
            }
            q0[u] = a0; q1[u] = a1; q2[u] = a2; q3[u] = a3; q4[u] = a4;

            if (++scur == RING) scur = 0;
            if (++spre == RING) spre = 0;

            // W-blur output w = w0 + j - 10 from ring rows j-10..j
            // (slot of row j-10+k is (u+1+k) % 11, compile-time).
            if (j >= 10) {
                float m0 = 0.f, m1 = 0.f, m2 = 0.f, m3 = 0.f, m4 = 0.f;
                #pragma unroll
                for (int k = 0; k < 11; ++k) {
                    const int sl = (u + 1 + k) % 11;
                    m0 = fmaf(GW[k], q0[sl], m0);
                    m1 = fmaf(GW[k], q1[sl], m1);
                    m2 = fmaf(GW[k], q2[sl], m2);
                    m3 = fmaf(GW[k], q3[sl], m3);
                    m4 = fmaf(GW[k], q4[sl], m4);
                }
                const size_t off = bh + (size_t)(w0 + j - 10) * HD + t;
                gC[0ULL * NVOX + off] = __float2half_rn(m0);
                gC[1ULL * NVOX + off] = __float2half_rn(m1);
                gC[2ULL * NVOX + off] = __float2half_rn(m2);
                gC[3ULL * NVOX + off] = __float2half_rn(m3);
                gC[4ULL * NVOX + off] = __float2half_rn(m4);
            }
        }
    }
}

// ---------------------------------------------------------------------------
// passH: H-blur + SSIM + reduce (R6 form). Block (h-seg 40, w, b), 160 thr.
// ---------------------------------------------------------------------------
__global__ void __launch_bounds__(HD) passH(float* __restrict__ out) {
    const int d  = threadIdx.x;
    const int b  = blockIdx.z;
    const int w  = blockIdx.y;
    const int h0 = blockIdx.x * SEG;

    const size_t bw = (size_t)b * VOL + (size_t)w * HD + d;

    float win[5][11];

    #pragma unroll
    for (int m = 0; m < 10; ++m) {
        const size_t off = bw + (size_t)refl(h0 - 5 + m) * PLN;
        #pragma unroll
        for (int f = 0; f < 5; ++f)
            win[f][m] = __half2float(__ldg(gC + (size_t)f * NVOX + off));
    }

    float acc = 0.f;

    #pragma unroll 1
    for (int c = 0; c < SEG / 11 + 1; ++c) {
        const int jbase = c * 11;
        #pragma unroll
        for (int u = 0; u < 11; ++u) {
            const int j = jbase + u;
            if (j >= SEG) break;
            {
                const size_t off = bw + (size_t)refl(h0 + j + 5) * PLN;
                #pragma unroll
                for (int f = 0; f < 5; ++f)
                    win[f][(u + 10) % 11] =
                        __half2float(__ldg(gC + (size_t)f * NVOX + off));
            }
            float mu1 = 0.f, mu2 = 0.f, m11 = 0.f, m22 = 0.f, m12 = 0.f;
            #pragma unroll
            for (int k = 0; k < 11; ++k) {
                const int sl = (u + k) % 11;
                mu1 = fmaf(GW[k], win[0][sl], mu1);
                mu2 = fmaf(GW[k], win[1][sl], mu2);
                m11 = fmaf(GW[k], win[2][sl], m11);
                m22 = fmaf(GW[k], win[3][sl], m22);
                m12 = fmaf(GW[k], win[4][sl], m12);
            }
            const float a  = mu1 * mu1;
            const float bb = mu2 * mu2;
            const float cc = mu1 * mu2;
            const float s1 = m11 - a, s2 = m22 - bb, s12 = m12 - cc;
            const float num = (2.f * cc + C1f) * (2.f * s12 + C2f);
            const float den = (a + bb + C1f) * (s1 + s2 + C2f);
            acc += __fdividef(num, den + EPSf);
        }
    }

    // Reduce: 5 warps -> smem -> atomicAdd(double), ticket finalize.
    float v = acc;
    #pragma unroll
    for (int o = 16; o > 0; o >>= 1) v += __shfl_down_sync(0xffffffffu, v, o);
    __shared__ float ws[5];
    if ((threadIdx.x & 31) == 0) ws[threadIdx.x >> 5] = v;
    __syncthreads();
    if (threadIdx.x == 0) {
        const float s = ws[0] + ws[1] + ws[2] + ws[3] + ws[4];
        atomicAdd(&g_acc, (double)s);
        __threadfence();
        const unsigned done = atomicAdd(&g_ticket, 1u);
        if (done == NBBC - 1) {
            const double vv = atomicAdd(&g_acc, 0.0);
            out[0] = (float)(1.0 - vv / (double)NVOX);
            g_acc = 0.0;
            g_ticket = 0u;
            __threadfence();
        }
    }
}

extern "C" void kernel_launch(void* const* d_in, const int* in_sizes, int n_in,
                              void* d_out, int out_size) {
    const float* src = (const float*)d_in[0];
    const float* ref = (const float*)d_in[1];
    float* out = (float*)d_out;

    passDW<<<dim3(HD / WSEG, HD, 2), HD>>>(src, ref);
    passH<<<dim3(NSEG, HD, 2), HD>>>(out);
}